// round 7
// baseline (speedup 1.0000x reference)
#include <cuda_runtime.h>
#include <cuda_bf16.h>
#include <mma.h>
#include <math.h>
#include <stdint.h>

using namespace nvcuda;

// Problem constants (fixed by the bench)
#define BATCH 8
#define CIN   64
#define COUT  64
#define NPT   2048
#define DTOT  192           // 3*Cin feature dim for kNN
#define KNN   11            // k+1
#define NPAIR (BATCH*NPT)   // 16384 points total
#define NEDGE (BATCH*NPT*KNN)
#define TCAND 20            // candidates kept per row before exact refine
#define CCAP  384           // per-row candidate collection capacity

#define VN_EPS 1e-6f
#define BN_EPS 1e-5f

// ---------------- scratch (device globals; no cudaMalloc allowed) ----------------
__device__ __nv_bfloat16  g_pb[(size_t)BATCH * NPT * NPT];      // 67 MB bf16 rank scores
__device__ float          g_rtm[(size_t)NPAIR * 32];            // per-row per-64col-group max
__device__ float          g_xt[(size_t)NPAIR * DTOT];           // transposed x: [bm][d]
__device__ __nv_bfloat16  g_hi[(size_t)NPAIR * DTOT];           // bf16 of xt
__device__ double         g_xx64[NPAIR];
__device__ float          g_mxx[NPAIR];                         // -0.5*xx (fp32)
__device__ int            g_cand[(size_t)NPAIR * TCAND];
__device__ int            g_idx[NEDGE];
__device__ float          g_yf[(size_t)NPAIR * DTOT];           // [bm][o*3+d]
__device__ float          g_yd[(size_t)NPAIR * DTOT];
__device__ float          g_nrm[(size_t)NPAIR * COUT];          // [bm][o]
__device__ float          g_dfd[(size_t)NPAIR * COUT];
__device__ float          g_dsq[(size_t)NPAIR * COUT];
__device__ float          g_v[(size_t)NPAIR * DTOT];            // per-point output vectors
__device__ int            g_cnt[NPAIR];
__device__ float          g_chA[COUT];
__device__ float          g_chB[COUT];

// ---------------- 0: transpose x -> g_xt [bm][d]; emit bf16 ----------------
__global__ void xt_kernel(const float* __restrict__ x) {
    __shared__ float t[32][33];
    int b  = blockIdx.z;
    int d0 = blockIdx.y * 32;
    int n0 = blockIdx.x * 32;
    const float* X = x + (size_t)b * DTOT * NPT;
    t[threadIdx.y][threadIdx.x] = X[(size_t)(d0 + threadIdx.y) * NPT + n0 + threadIdx.x];
    __syncthreads();
    float v = t[threadIdx.x][threadIdx.y];
    size_t o = ((size_t)(b << 11) + n0 + threadIdx.y) * DTOT + d0 + threadIdx.x;
    g_xt[o] = v;
    g_hi[o] = __float2bfloat16(v);
}

// ---------------- 1: xx in fp64 (exact) + fp32 -0.5*xx; zero counts ----------------
__global__ void xx64_kernel() {
    int p = blockIdx.x * blockDim.x + threadIdx.x;      // 16384 points
    const float* r = g_xt + (size_t)p * DTOT;
    double s = 0.0;
    #pragma unroll 8
    for (int d = 0; d < DTOT; d++) { double v = (double)r[d]; s += v * v; }
    g_xx64[p] = s;
    g_mxx[p] = (float)(-0.5 * s);
    g_cnt[p] = 0;
}

// ---------------- 2: whole-K-resident wmma rank-score GEMM ----------------
// score[n][m] = x_n.x_m - 0.5*xx_m  (per-row-monotone transform of pdist), stored bf16
#define SLDA 200   // bf16 leading dim for A/B smem tiles (400B rows, 16B aligned)
#define SLDS 260   // float leading dim for epilogue stage (1040B rows)
// dynamic smem layout:
//   sA bf16[128][SLDA] @ 0        (51200 B)
//   sB bf16[256][SLDA] @ 51200    (102400 B)
//   sxx float[256]     @ 153600   (1024 B)     -> total 154624
//   stage float[128][SLDS] @ 0    (133120 B, reuses sA/sB after mainloop)
#define KNN_SMEM 154624

__global__ __launch_bounds__(256, 1) void knn_wmma2() {
    extern __shared__ __align__(16) char dsm[];
    __nv_bfloat16* sA  = (__nv_bfloat16*)dsm;
    __nv_bfloat16* sB  = (__nv_bfloat16*)(dsm + 51200);
    float*         sxx = (float*)(dsm + 153600);
    float*         stage = (float*)dsm;

    int tid  = threadIdx.x;
    int warp = tid >> 5;
    int wm   = warp & 1;    // 2 warps along rows (n), 64 rows each
    int wn   = warp >> 1;   // 4 warps along cols (m), 64 cols each
    int n0 = blockIdx.y * 128;
    int m0 = blockIdx.x * 256;
    int bb = blockIdx.z << 11;

    // load tiles (whole K resident; rows are 24 int4 of 8 bf16)
    for (int i = tid; i < 3072; i += 256) {
        int row = i / 24; int c8 = (i - row * 24) * 8;
        *(int4*)&sA[row * SLDA + c8] = *(const int4*)&g_hi[(size_t)(bb + n0 + row) * DTOT + c8];
    }
    for (int i = tid; i < 6144; i += 256) {
        int row = i / 24; int c8 = (i - row * 24) * 8;
        *(int4*)&sB[row * SLDA + c8] = *(const int4*)&g_hi[(size_t)(bb + m0 + row) * DTOT + c8];
    }
    sxx[tid] = g_mxx[bb + m0 + tid];
    __syncthreads();

    wmma::fragment<wmma::accumulator, 16, 16, 16, float> cf[4][4];
    #pragma unroll
    for (int i = 0; i < 4; i++)
        #pragma unroll
        for (int j = 0; j < 4; j++) wmma::fill_fragment(cf[i][j], 0.0f);

    // mainloop: K = 192 = 12 x 16, no syncs
    #pragma unroll 3
    for (int k = 0; k < 12; k++) {
        wmma::fragment<wmma::matrix_a, 16, 16, 16, __nv_bfloat16, wmma::row_major> af[4];
        wmma::fragment<wmma::matrix_b, 16, 16, 16, __nv_bfloat16, wmma::col_major> bfr[4];
        #pragma unroll
        for (int i = 0; i < 4; i++)
            wmma::load_matrix_sync(af[i], &sA[(wm * 64 + i * 16) * SLDA + k * 16], SLDA);
        #pragma unroll
        for (int j = 0; j < 4; j++)
            wmma::load_matrix_sync(bfr[j], &sB[(wn * 64 + j * 16) * SLDA + k * 16], SLDA);
        #pragma unroll
        for (int i = 0; i < 4; i++)
            #pragma unroll
            for (int j = 0; j < 4; j++)
                wmma::mma_sync(cf[i][j], af[i], bfr[j], cf[i][j]);
    }
    __syncthreads();   // tiles fully consumed; safe to reuse smem as stage

    #pragma unroll
    for (int i = 0; i < 4; i++)
        #pragma unroll
        for (int j = 0; j < 4; j++)
            wmma::store_matrix_sync(&stage[(wm * 64 + i * 16) * SLDS + wn * 64 + j * 16],
                                    cf[i][j], SLDS, wmma::mem_row_major);
    __syncthreads();

    // epilogue: thread owns (row, 128-col half): add -0.5*xx_m, round to bf16,
    // per-64-col group max, coalesced-ish bf16 store
    {
        int row = tid >> 1, half = tid & 1;
        const float* srow = stage + row * SLDS + half * 128;
        const float* sx   = sxx + half * 128;
        __nv_bfloat16* orow = g_pb + (size_t)(bb + n0 + row) * NPT + m0 + half * 128;
        #pragma unroll
        for (int g = 0; g < 2; g++) {
            float gm = -INFINITY;
            #pragma unroll
            for (int c0 = 0; c0 < 64; c0 += 8) {
                __nv_bfloat16 tb[8];
                #pragma unroll
                for (int e = 0; e < 8; e++) {
                    float v = srow[g * 64 + c0 + e] + sx[g * 64 + c0 + e];
                    __nv_bfloat16 h = __float2bfloat16(v);
                    tb[e] = h;
                    gm = fmaxf(gm, __bfloat162float(h));
                }
                *(uint4*)&orow[g * 64 + c0] = *(uint4*)tb;
            }
            g_rtm[(size_t)(bb + n0 + row) * 32 + blockIdx.x * 4 + half * 2 + g] = gm;
        }
    }
}

// ---------------- 3: threshold-collect top-TCAND per row (warp per row, bf16) ----------------
__device__ __forceinline__ void unp8(uint4 u, float* v) {
    const __nv_bfloat162* p = (const __nv_bfloat162*)&u;
    #pragma unroll
    for (int j = 0; j < 4; j++) {
        float2 f = __bfloat1622float2(p[j]);
        v[2 * j] = f.x; v[2 * j + 1] = f.y;
    }
}
__global__ __launch_bounds__(256) void cand_kernel() {
    int gwarp = (blockIdx.x * blockDim.x + threadIdx.x) >> 5;   // row id [0,16384)
    int lane  = threadIdx.x & 31;
    int wl    = threadIdx.x >> 5;

    __shared__ float s_v[8][CCAP];
    __shared__ int   s_i[8][CCAP];

    // tau = min of the 32 group maxima (guarantees >=32 elements >= tau)
    float tm = g_rtm[(size_t)gwarp * 32 + lane];
    #pragma unroll
    for (int off = 16; off; off >>= 1) tm = fminf(tm, __shfl_down_sync(0xffffffff, tm, off));
    float tau = __shfl_sync(0xffffffff, tm, 0);

    const uint4* rowp = (const uint4*)(g_pb + (size_t)gwarp * NPT);   // 256 x (8 bf16)
    int base = 0;
    for (int i = 0; i < 4; i++) {
        int qa = i * 64 + lane;
        int qb = qa + 32;
        uint4 A = rowp[qa];
        uint4 B = rowp[qb];
        float vals[16];
        unp8(A, vals);
        unp8(B, vals + 8);
        float mx = vals[0];
        #pragma unroll
        for (int c = 1; c < 16; c++) mx = fmaxf(mx, vals[c]);
        unsigned any = __ballot_sync(0xffffffff, mx >= tau);
        if (any) {
            #pragma unroll
            for (int c = 0; c < 16; c++) {
                bool hit = vals[c] >= tau;
                unsigned m = __ballot_sync(0xffffffff, hit);
                if (m) {
                    if (hit) {
                        int pos = base + __popc(m & ((1u << lane) - 1));
                        int q = (c < 8) ? qa : qb;
                        if (pos < CCAP) { s_v[wl][pos] = vals[c]; s_i[wl][pos] = q * 8 + (c & 7); }
                    }
                    base += __popc(m);
                }
            }
        }
    }
    int cnt = min(base, CCAP);
    __syncwarp();

    // top-TCAND of collected (value desc, index asc)
    int* out = g_cand + (size_t)gwarp * TCAND;
    for (int r = 0; r < TCAND; r++) {
        float bv = -INFINITY; int bi = 0x7fffffff;
        for (int t = lane; t < cnt; t += 32) {
            float vv = s_v[wl][t]; int ii = s_i[wl][t];
            if (vv > bv || (vv == bv && ii < bi)) { bv = vv; bi = ii; }
        }
        #pragma unroll
        for (int off = 16; off; off >>= 1) {
            float ov = __shfl_down_sync(0xffffffff, bv, off);
            int   oi = __shfl_down_sync(0xffffffff, bi, off);
            if (ov > bv || (ov == bv && oi < bi)) { bv = ov; bi = oi; }
        }
        bv = __shfl_sync(0xffffffff, bv, 0);
        bi = __shfl_sync(0xffffffff, bi, 0);
        if (lane == 0) out[r] = bi;
        for (int t = lane; t < cnt; t += 32)
            if (s_i[wl][t] == bi) s_v[wl][t] = -INFINITY;
        __syncwarp();
    }
}

// ---------------- 4: exact fp64 refine of candidates -> final top-KNN ----------------
__global__ __launch_bounds__(256) void refine_kernel() {
    int row  = (blockIdx.x * blockDim.x + threadIdx.x) >> 5;  // [0,16384)
    int lane = threadIdx.x & 31;
    int wl   = threadIdx.x >> 5;
    int b    = row >> 11;

    __shared__ float s_val[8][TCAND];
    __shared__ int   s_id[8][TCAND];

    float xn[6];
    #pragma unroll
    for (int u = 0; u < 6; u++) xn[u] = g_xt[(size_t)row * DTOT + lane + 32 * u];
    float xxn = (float)g_xx64[row];

    for (int j = 0; j < TCAND; j++) {
        int m = g_cand[(size_t)row * TCAND + j];
        const float* xm = g_xt + ((size_t)(b << 11) + m) * DTOT;
        double acc = 0.0;
        #pragma unroll
        for (int u = 0; u < 6; u++) acc += (double)xn[u] * (double)xm[lane + 32 * u];
        #pragma unroll
        for (int off = 16; off; off >>= 1) acc += __shfl_down_sync(0xffffffff, acc, off);
        if (lane == 0) {
            // emulate reference's fp32 expression structure for tie alignment:
            float innerf = (float)acc;
            float pf = 2.0f * innerf;
            pf = pf - xxn;
            pf = pf - (float)g_xx64[(size_t)(b << 11) + m];
            s_val[wl][j] = pf;
            s_id[wl][j]  = m;
        }
    }
    __syncwarp();

    if (lane == 0) {
        int* out = g_idx + (size_t)row * KNN;
        for (int r = 0; r < KNN; r++) {
            float bv = -INFINITY; int bi = 0x7fffffff; int bs = 0;
            #pragma unroll
            for (int t = 0; t < TCAND; t++) {
                float v = s_val[wl][t]; int id = s_id[wl][t];
                if (v > bv || (v == bv && id < bi)) { bv = v; bi = id; bs = t; }
            }
            out[r] = bi;
            s_val[wl][bs] = -INFINITY;
        }
    }
}

// ---------------- 5: y_feat / y_dir  [bm][od] ----------------
__global__ void feat_kernel(const float* __restrict__ x,
                            const float* __restrict__ Wf,
                            const float* __restrict__ Wd) {
    __shared__ float wfs[64][64];   // [c][o]
    __shared__ float wds[64][64];
    __shared__ float xs[DTOT][16];

    int b = blockIdx.y;
    int n0 = blockIdx.x * 16;
    int tid = threadIdx.x;          // 192

    for (int i = tid; i < 4096; i += 192) {
        int o = i >> 6, c = i & 63;
        wfs[c][o] = Wf[i];
        wds[c][o] = Wd[i];
    }
    const float* X = x + (size_t)b * DTOT * NPT;
    for (int i = tid; i < DTOT * 16; i += 192) {
        int c3 = i >> 4, n = i & 15;
        xs[c3][n] = X[(size_t)c3 * NPT + n0 + n];
    }
    __syncthreads();

    int o = tid / 3;
    int d = tid - 3 * o;

    float af[16], ad_[16];
    #pragma unroll
    for (int n = 0; n < 16; n++) { af[n] = 0.f; ad_[n] = 0.f; }

    for (int c = 0; c < 64; c++) {
        float wf = wfs[c][o], wd = wds[c][o];
        #pragma unroll
        for (int n = 0; n < 16; n++) {
            float xv = xs[c * 3 + d][n];
            af[n]  = fmaf(wf, xv, af[n]);
            ad_[n] = fmaf(wd, xv, ad_[n]);
        }
    }
    #pragma unroll
    for (int n = 0; n < 16; n++) {
        size_t base = ((size_t)b * NPT + n0 + n) * DTOT + tid;
        g_yf[base] = af[n];
        g_yd[base] = ad_[n];
    }
}

// ---------------- 6: per-point norm / f·d / |d|^2 ----------------
__global__ void pstat_kernel() {
    int t = blockIdx.x * blockDim.x + threadIdx.x;  // 16384*64
    int bm = t >> 6;
    int o  = t & 63;
    const float* f = g_yf + (size_t)bm * DTOT + o * 3;
    const float* g = g_yd + (size_t)bm * DTOT + o * 3;
    float f0 = f[0], f1 = f[1], f2 = f[2];
    float g0 = g[0], g1 = g[1], g2 = g[2];
    g_nrm[t] = sqrtf(f0 * f0 + f1 * f1 + f2 * f2);
    g_dfd[t] = f0 * g0 + f1 * g1 + f2 * g2;
    g_dsq[t] = g0 * g0 + g1 * g1 + g2 * g2;
}

// ---------------- 7: neighbor counts ----------------
__global__ void count_kernel() {
    int t = blockIdx.x * blockDim.x + threadIdx.x;  // NEDGE = 180224
    if (t < NEDGE) {
        int b = t / (NPT * KNN);
        atomicAdd(&g_cnt[b * NPT + g_idx[t]], 1);
    }
}

// ---------------- 8: BN stats (count-weighted, exact) ----------------
__global__ void bnstat_kernel(const float* __restrict__ gamma, const float* __restrict__ beta) {
    int o = blockIdx.x;
    int tid = threadIdx.x;  // 256
    double s1 = 0.0, s2 = 0.0;
    for (int bm = tid; bm < NPAIR; bm += 256) {
        float v = g_nrm[(size_t)bm * COUT + o];
        double c = (double)g_cnt[bm];
        s1 += c * v;
        s2 += c * (double)v * (double)v;
    }
    __shared__ double r1[256], r2[256];
    r1[tid] = s1; r2[tid] = s2;
    __syncthreads();
    for (int s = 128; s; s >>= 1) {
        if (tid < s) { r1[tid] += r1[tid + s]; r2[tid] += r2[tid + s]; }
        __syncthreads();
    }
    if (tid == 0) {
        const double cnt = (double)NEDGE;
        double mean = r1[0] / cnt;
        double var  = r2[0] / cnt - mean * mean;
        double a = (double)gamma[o] / sqrt(var + (double)BN_EPS);
        g_chA[o] = (float)a;
        g_chB[o] = (float)((double)beta[o] - mean * a);
    }
}

// ---------------- 9: per-point output vectors v ----------------
__global__ void v_kernel() {
    int bm = blockIdx.x;
    int od = threadIdx.x;       // 192
    int o = od / 3;
    size_t t = (size_t)bm * DTOT + od;
    size_t s = (size_t)bm * COUT + o;
    float n    = g_nrm[s];
    float scale = g_chA[o] + g_chB[o] / n;     // norm_bn / norm
    float dot  = scale * g_dfd[s];
    float pv   = scale * g_yf[t];
    float outv = pv;
    if (dot < 0.f) outv = pv - dot / (g_dsq[s] + VN_EPS) * g_yd[t];
    g_v[t] = outv;
}

// ---------------- 10: gather-mean to output ----------------
__global__ void gather_kernel(float* __restrict__ out) {
    __shared__ int sidx[16 * KNN];
    int b  = blockIdx.y;
    int n0 = blockIdx.x * 16;
    int tid = threadIdx.x;      // 192
    if (tid < 16 * KNN) sidx[tid] = g_idx[((size_t)b * NPT + n0) * KNN + tid];
    __syncthreads();

    const float* vb = g_v + (size_t)b * NPT * DTOT;
    float res[16];
    #pragma unroll
    for (int n = 0; n < 16; n++) {
        float acc = 0.f;
        #pragma unroll
        for (int k = 0; k < KNN; k++) {
            int m = sidx[n * KNN + k];
            acc += vb[(size_t)m * DTOT + tid];
        }
        res[n] = acc * (1.0f / (float)KNN);
    }
    float* ob = out + ((size_t)b * DTOT + tid) * NPT + n0;
    *(float4*)(ob)      = make_float4(res[0],  res[1],  res[2],  res[3]);
    *(float4*)(ob + 4)  = make_float4(res[4],  res[5],  res[6],  res[7]);
    *(float4*)(ob + 8)  = make_float4(res[8],  res[9],  res[10], res[11]);
    *(float4*)(ob + 12) = make_float4(res[12], res[13], res[14], res[15]);
}

// ---------------- launch ----------------
extern "C" void kernel_launch(void* const* d_in, const int* in_sizes, int n_in,
                              void* d_out, int out_size) {
    const float* x     = (const float*)d_in[0];
    const float* Wf    = (const float*)d_in[1];
    const float* Wd    = (const float*)d_in[2];
    const float* gamma = (const float*)d_in[3];
    const float* beta  = (const float*)d_in[4];
    float* out = (float*)d_out;

    cudaFuncSetAttribute(knn_wmma2, cudaFuncAttributeMaxDynamicSharedMemorySize, KNN_SMEM);

    xt_kernel<<<dim3(NPT / 32, DTOT / 32, BATCH), dim3(32, 32)>>>(x);
    xx64_kernel<<<NPAIR / 256, 256>>>();
    knn_wmma2<<<dim3(NPT / 256, NPT / 128, BATCH), 256, KNN_SMEM>>>();
    cand_kernel<<<NPAIR / 8, 256>>>();
    refine_kernel<<<NPAIR / 8, 256>>>();
    feat_kernel<<<dim3(NPT / 16, BATCH), 192>>>(x, Wf, Wd);
    pstat_kernel<<<(NPAIR * COUT) / 256, 256>>>();
    count_kernel<<<(NEDGE + 255) / 256, 256>>>();
    bnstat_kernel<<<COUT, 256>>>(gamma, beta);
    v_kernel<<<NPAIR, DTOT>>>();
    gather_kernel<<<dim3(NPT / 16, BATCH), DTOT>>>(out);
}

// round 8
// speedup vs baseline: 1.7675x; 1.7675x over previous
#include <cuda_runtime.h>
#include <cuda_bf16.h>
#include <mma.h>
#include <math.h>

using namespace nvcuda;

// Problem constants (fixed by the bench)
#define BATCH 8
#define CIN   64
#define COUT  64
#define NPT   2048
#define DTOT  192           // 3*Cin feature dim for kNN
#define KNN   11            // k+1
#define NPAIR (BATCH*NPT)   // 16384 points total
#define NEDGE (BATCH*NPT*KNN)
#define TCAND 16            // candidates kept per row before exact refine
#define CCAP  320           // per-row candidate collection capacity

#define VN_EPS 1e-6f
#define BN_EPS 1e-5f

// ---------------- scratch (device globals; no cudaMalloc allowed) ----------------
__device__ float          g_pdist[(size_t)BATCH * NPT * NPT];   // 134 MB (rank scores)
__device__ float          g_rtm[(size_t)NPAIR * 16];            // per-row per-128-tile max
__device__ float          g_xt[(size_t)NPAIR * DTOT];           // transposed x: [bm][d]
__device__ __nv_bfloat16  g_hi[(size_t)NPAIR * DTOT];           // bf16 of xt
__device__ double         g_xx64[NPAIR];
__device__ __nv_bfloat16  g_hx[NPAIR];                          // bf16 hi of -0.5*xx
__device__ __nv_bfloat16  g_lx[NPAIR];                          // bf16 lo of -0.5*xx
__device__ int            g_cand[(size_t)NPAIR * TCAND];
__device__ int            g_idx[NEDGE];
__device__ float          g_yf[(size_t)NPAIR * DTOT];           // [bm][o*3+d]
__device__ float          g_yd[(size_t)NPAIR * DTOT];
__device__ float          g_nrm[(size_t)NPAIR * COUT];          // [bm][o]
__device__ float          g_dfd[(size_t)NPAIR * COUT];
__device__ float          g_dsq[(size_t)NPAIR * COUT];
__device__ float          g_v[(size_t)NPAIR * DTOT];            // per-point output vectors
__device__ int            g_cnt[NPAIR];
__device__ float          g_chA[COUT];
__device__ float          g_chB[COUT];

// ---------------- 0: transpose x -> g_xt [bm][d]; emit bf16 ----------------
__global__ void xt_kernel(const float* __restrict__ x) {
    __shared__ float t[32][33];
    int b  = blockIdx.z;
    int d0 = blockIdx.y * 32;
    int n0 = blockIdx.x * 32;
    const float* X = x + (size_t)b * DTOT * NPT;
    t[threadIdx.y][threadIdx.x] = X[(size_t)(d0 + threadIdx.y) * NPT + n0 + threadIdx.x];
    __syncthreads();
    float v = t[threadIdx.x][threadIdx.y];
    size_t o = ((size_t)(b << 11) + n0 + threadIdx.y) * DTOT + d0 + threadIdx.x;
    g_xt[o] = v;
    g_hi[o] = __float2bfloat16(v);
}

// ---------------- 1: xx in fp64 (exact) + bf16 hi/lo of -0.5*xx; zero counts ----------------
__global__ void xx64_kernel() {
    int p = blockIdx.x * blockDim.x + threadIdx.x;      // 16384 points
    const float* r = g_xt + (size_t)p * DTOT;
    double s = 0.0;
    #pragma unroll 8
    for (int d = 0; d < DTOT; d++) { double v = (double)r[d]; s += v * v; }
    g_xx64[p] = s;
    float m05 = (float)(-0.5 * s);
    __nv_bfloat16 hx = __float2bfloat16(m05);
    g_hx[p] = hx;
    g_lx[p] = __float2bfloat16(m05 - __bfloat162float(hx));
    g_cnt[p] = 0;
}

// ---------------- 2: tensor-core rank-score GEMM + per-row tile max ----------------
// score[n][m] = x_n.x_m - 0.5*xx_m   (per-row-monotone transform of pdist)
#define SMLD 40   // smem row stride (bf16 elems), pad 8 to kill conflicts
__global__ __launch_bounds__(256) void knn_wmma() {
    int b  = blockIdx.z;
    int n0 = blockIdx.y * 128;
    int m0 = blockIdx.x * 128;
    int bb = b << 11;

    __shared__ __nv_bfloat16 sA[128][SMLD];
    __shared__ __nv_bfloat16 sB[128][SMLD];

    int tid  = threadIdx.x;
    int warp = tid >> 5;
    int wm   = warp & 1;    // 2 warps along rows (n)
    int wn   = warp >> 1;   // 4 warps along cols (m)

    wmma::fragment<wmma::accumulator, 16, 16, 16, float> cf[4][2];
    #pragma unroll
    for (int i = 0; i < 4; i++)
        #pragma unroll
        for (int j = 0; j < 2; j++) wmma::fill_fragment(cf[i][j], 0.0f);

    // 6 chunks of BK=32 over K=192, single bf16 term
    for (int t = 0; t < 6; t++) {
        int dof = t * 32;
        #pragma unroll
        for (int r = 0; r < 2; r++) {
            int idx = tid + r * 256;        // 512 int4 slots per tile
            int row = idx >> 2;
            int c8  = (idx & 3) * 8;
            *(int4*)&sA[row][c8] = *(const int4*)&g_hi[(size_t)(bb + n0 + row) * DTOT + dof + c8];
            *(int4*)&sB[row][c8] = *(const int4*)&g_hi[(size_t)(bb + m0 + row) * DTOT + dof + c8];
        }
        __syncthreads();
        #pragma unroll
        for (int kk = 0; kk < 32; kk += 16) {
            wmma::fragment<wmma::matrix_a, 16, 16, 16, __nv_bfloat16, wmma::row_major> af[4];
            wmma::fragment<wmma::matrix_b, 16, 16, 16, __nv_bfloat16, wmma::col_major> bfr[2];
            #pragma unroll
            for (int i = 0; i < 4; i++)
                wmma::load_matrix_sync(af[i], &sA[wm * 64 + i * 16][kk], SMLD);
            #pragma unroll
            for (int j = 0; j < 2; j++)
                wmma::load_matrix_sync(bfr[j], &sB[wn * 32 + j * 16][kk], SMLD);
            #pragma unroll
            for (int i = 0; i < 4; i++)
                #pragma unroll
                for (int j = 0; j < 2; j++)
                    wmma::mma_sync(cf[i][j], af[i], bfr[j], cf[i][j]);
        }
        __syncthreads();
    }

    // augmented tail k16: A=[1,1,0..], B=[hx_m,lx_m,0..]  -> adds -0.5*xx_m
    {
        const __nv_bfloat16 one = __float2bfloat16(1.0f);
        const __nv_bfloat16 zero = __float2bfloat16(0.0f);
        if (tid < 128) {
            int row = tid;
            sA[row][0] = one; sA[row][1] = one;
            #pragma unroll
            for (int c = 2; c < 16; c++) sA[row][c] = zero;
        } else {
            int row = tid - 128;
            sB[row][0] = g_hx[bb + m0 + row];
            sB[row][1] = g_lx[bb + m0 + row];
            #pragma unroll
            for (int c = 2; c < 16; c++) sB[row][c] = zero;
        }
        __syncthreads();
        wmma::fragment<wmma::matrix_a, 16, 16, 16, __nv_bfloat16, wmma::row_major> af[4];
        wmma::fragment<wmma::matrix_b, 16, 16, 16, __nv_bfloat16, wmma::col_major> bfr[2];
        #pragma unroll
        for (int i = 0; i < 4; i++)
            wmma::load_matrix_sync(af[i], &sA[wm * 64 + i * 16][0], SMLD);
        #pragma unroll
        for (int j = 0; j < 2; j++)
            wmma::load_matrix_sync(bfr[j], &sB[wn * 32 + j * 16][0], SMLD);
        #pragma unroll
        for (int i = 0; i < 4; i++)
            #pragma unroll
            for (int j = 0; j < 2; j++)
                wmma::mma_sync(cf[i][j], af[i], bfr[j], cf[i][j]);
    }

    // store raw scores
    #pragma unroll
    for (int i = 0; i < 4; i++)
        #pragma unroll
        for (int j = 0; j < 2; j++) {
            float* op = g_pdist + ((size_t)(bb + n0 + wm * 64 + i * 16)) * NPT
                        + m0 + wn * 32 + j * 16;
            wmma::store_matrix_sync(op, cf[i][j], NPT, wmma::mem_row_major);
        }

    // per-row max of this 128x128 tile (reads back own stores; block-visible after sync)
    __syncthreads();
    {
        float* smax = (float*)&sA[0][0];          // reuse smem
        int row  = tid >> 1;
        int half = tid & 1;
        const float4* p = (const float4*)(g_pdist + (size_t)(bb + n0 + row) * NPT + m0 + half * 64);
        float mx = -INFINITY;
        #pragma unroll
        for (int j = 0; j < 16; j++) {
            float4 v = p[j];
            mx = fmaxf(mx, fmaxf(fmaxf(v.x, v.y), fmaxf(v.z, v.w)));
        }
        smax[row * 2 + half] = mx;
        __syncthreads();
        if (tid < 128)
            g_rtm[(size_t)(bb + n0 + tid) * 16 + blockIdx.x] = fmaxf(smax[tid * 2], smax[tid * 2 + 1]);
    }
}

// ---------------- 3: threshold-collect top-TCAND per row (warp per row) ----------------
__global__ __launch_bounds__(256) void cand_kernel() {
    int gwarp = (blockIdx.x * blockDim.x + threadIdx.x) >> 5;   // row id [0,16384)
    int lane  = threadIdx.x & 31;
    int wl    = threadIdx.x >> 5;

    __shared__ float s_v[8][CCAP];
    __shared__ int   s_i[8][CCAP];

    // tau = min of the 16 tile maxima  (guarantees >=16 elements >= tau)
    float tm = (lane < 16) ? g_rtm[(size_t)gwarp * 16 + lane] : INFINITY;
    #pragma unroll
    for (int off = 8; off; off >>= 1) tm = fminf(tm, __shfl_down_sync(0xffffffff, tm, off));
    float tau = __shfl_sync(0xffffffff, tm, 0);

    const float4* row4 = (const float4*)(g_pdist + (size_t)gwarp * NPT);
    int base = 0;
    #pragma unroll 2
    for (int i = 0; i < NPT / 128; i++) {
        int q = i * 32 + lane;
        float4 v = row4[q];
        float mx = fmaxf(fmaxf(v.x, v.y), fmaxf(v.z, v.w));
        unsigned any = __ballot_sync(0xffffffff, mx >= tau);
        if (any) {
            float vals[4] = {v.x, v.y, v.z, v.w};
            #pragma unroll
            for (int c = 0; c < 4; c++) {
                bool hit = vals[c] >= tau;
                unsigned m = __ballot_sync(0xffffffff, hit);
                if (m) {
                    if (hit) {
                        int pos = base + __popc(m & ((1u << lane) - 1));
                        if (pos < CCAP) { s_v[wl][pos] = vals[c]; s_i[wl][pos] = q * 4 + c; }
                    }
                    base += __popc(m);
                }
            }
        }
    }
    int cnt = min(base, CCAP);
    __syncwarp();

    // top-TCAND of collected (value desc, index asc)
    int* out = g_cand + (size_t)gwarp * TCAND;
    for (int r = 0; r < TCAND; r++) {
        float bv = -INFINITY; int bi = 0x7fffffff;
        for (int t = lane; t < cnt; t += 32) {
            float vv = s_v[wl][t]; int ii = s_i[wl][t];
            if (vv > bv || (vv == bv && ii < bi)) { bv = vv; bi = ii; }
        }
        #pragma unroll
        for (int off = 16; off; off >>= 1) {
            float ov = __shfl_down_sync(0xffffffff, bv, off);
            int   oi = __shfl_down_sync(0xffffffff, bi, off);
            if (ov > bv || (ov == bv && oi < bi)) { bv = ov; bi = oi; }
        }
        bv = __shfl_sync(0xffffffff, bv, 0);
        bi = __shfl_sync(0xffffffff, bi, 0);
        if (lane == 0) out[r] = bi;
        for (int t = lane; t < cnt; t += 32)
            if (s_i[wl][t] == bi) s_v[wl][t] = -INFINITY;
        __syncwarp();
    }
}

// ---------------- 4: compensated-fp32 (Dot2) refine of candidates -> final top-KNN ----------------
// TwoProd + Knuth TwoSum via __f*_rn intrinsics (immune to fast-math reassociation).
// Error ~O(u^2 * n): effectively exact at fp32-comparison granularity, same as fp64 path.
__global__ __launch_bounds__(256) void refine_kernel() {
    int row  = (blockIdx.x * blockDim.x + threadIdx.x) >> 5;  // [0,16384)
    int lane = threadIdx.x & 31;
    int wl   = threadIdx.x >> 5;
    int b    = row >> 11;

    __shared__ float s_val[8][TCAND];
    __shared__ int   s_id[8][TCAND];

    float xn[6];
    #pragma unroll
    for (int u = 0; u < 6; u++) xn[u] = g_xt[(size_t)row * DTOT + lane + 32 * u];
    float xxn = (float)g_xx64[row];

    for (int j = 0; j < TCAND; j++) {
        int m = g_cand[(size_t)row * TCAND + j];
        const float* xm = g_xt + ((size_t)(b << 11) + m) * DTOT;
        float s = 0.0f, comp = 0.0f;
        #pragma unroll
        for (int u = 0; u < 6; u++) {
            float a = xn[u], bv = xm[lane + 32 * u];
            float p  = __fmul_rn(a, bv);
            float pe = __fmaf_rn(a, bv, -p);              // exact product error
            float t  = __fadd_rn(s, p);                   // Knuth TwoSum
            float z  = __fsub_rn(t, s);
            float e  = __fadd_rn(__fsub_rn(s, __fsub_rn(t, z)), __fsub_rn(p, z));
            s = t;
            comp = __fadd_rn(comp, __fadd_rn(e, pe));
        }
        #pragma unroll
        for (int off = 16; off; off >>= 1) {
            float os = __shfl_down_sync(0xffffffff, s,    off);
            float oc = __shfl_down_sync(0xffffffff, comp, off);
            float t  = __fadd_rn(s, os);
            float z  = __fsub_rn(t, s);
            float e  = __fadd_rn(__fsub_rn(s, __fsub_rn(t, z)), __fsub_rn(os, z));
            s = t;
            comp = __fadd_rn(comp, __fadd_rn(e, oc));
        }
        if (lane == 0) {
            // emulate reference's fp32 expression structure for tie alignment:
            float innerf = __fadd_rn(s, comp);
            float pf = 2.0f * innerf;
            pf = pf - xxn;
            pf = pf - (float)g_xx64[(size_t)(b << 11) + m];
            s_val[wl][j] = pf;
            s_id[wl][j]  = m;
        }
    }
    __syncwarp();

    if (lane == 0) {
        int* out = g_idx + (size_t)row * KNN;
        for (int r = 0; r < KNN; r++) {
            float bv = -INFINITY; int bi = 0x7fffffff; int bs = 0;
            #pragma unroll
            for (int t = 0; t < TCAND; t++) {
                float v = s_val[wl][t]; int id = s_id[wl][t];
                if (v > bv || (v == bv && id < bi)) { bv = v; bi = id; bs = t; }
            }
            out[r] = bi;
            s_val[wl][bs] = -INFINITY;
        }
    }
}

// ---------------- 5: y_feat / y_dir  [bm][od] ----------------
__global__ void feat_kernel(const float* __restrict__ x,
                            const float* __restrict__ Wf,
                            const float* __restrict__ Wd) {
    __shared__ float wfs[64][64];   // [c][o]
    __shared__ float wds[64][64];
    __shared__ float xs[DTOT][16];

    int b = blockIdx.y;
    int n0 = blockIdx.x * 16;
    int tid = threadIdx.x;          // 192

    for (int i = tid; i < 4096; i += 192) {
        int o = i >> 6, c = i & 63;
        wfs[c][o] = Wf[i];
        wds[c][o] = Wd[i];
    }
    const float* X = x + (size_t)b * DTOT * NPT;
    for (int i = tid; i < DTOT * 16; i += 192) {
        int c3 = i >> 4, n = i & 15;
        xs[c3][n] = X[(size_t)c3 * NPT + n0 + n];
    }
    __syncthreads();

    int o = tid / 3;
    int d = tid - 3 * o;

    float af[16], ad_[16];
    #pragma unroll
    for (int n = 0; n < 16; n++) { af[n] = 0.f; ad_[n] = 0.f; }

    for (int c = 0; c < 64; c++) {
        float wf = wfs[c][o], wd = wds[c][o];
        #pragma unroll
        for (int n = 0; n < 16; n++) {
            float xv = xs[c * 3 + d][n];
            af[n]  = fmaf(wf, xv, af[n]);
            ad_[n] = fmaf(wd, xv, ad_[n]);
        }
    }
    #pragma unroll
    for (int n = 0; n < 16; n++) {
        size_t base = ((size_t)b * NPT + n0 + n) * DTOT + tid;
        g_yf[base] = af[n];
        g_yd[base] = ad_[n];
    }
}

// ---------------- 6: per-point norm / f·d / |d|^2 ----------------
__global__ void pstat_kernel() {
    int t = blockIdx.x * blockDim.x + threadIdx.x;  // 16384*64
    int bm = t >> 6;
    int o  = t & 63;
    const float* f = g_yf + (size_t)bm * DTOT + o * 3;
    const float* g = g_yd + (size_t)bm * DTOT + o * 3;
    float f0 = f[0], f1 = f[1], f2 = f[2];
    float g0 = g[0], g1 = g[1], g2 = g[2];
    g_nrm[t] = sqrtf(f0 * f0 + f1 * f1 + f2 * f2);
    g_dfd[t] = f0 * g0 + f1 * g1 + f2 * g2;
    g_dsq[t] = g0 * g0 + g1 * g1 + g2 * g2;
}

// ---------------- 7: neighbor counts ----------------
__global__ void count_kernel() {
    int t = blockIdx.x * blockDim.x + threadIdx.x;  // NEDGE = 180224
    if (t < NEDGE) {
        int b = t / (NPT * KNN);
        atomicAdd(&g_cnt[b * NPT + g_idx[t]], 1);
    }
}

// ---------------- 8: BN stats (count-weighted, exact) ----------------
__global__ void bnstat_kernel(const float* __restrict__ gamma, const float* __restrict__ beta) {
    int o = blockIdx.x;
    int tid = threadIdx.x;  // 256
    double s1 = 0.0, s2 = 0.0;
    for (int bm = tid; bm < NPAIR; bm += 256) {
        float v = g_nrm[(size_t)bm * COUT + o];
        double c = (double)g_cnt[bm];
        s1 += c * v;
        s2 += c * (double)v * (double)v;
    }
    __shared__ double r1[256], r2[256];
    r1[tid] = s1; r2[tid] = s2;
    __syncthreads();
    for (int s = 128; s; s >>= 1) {
        if (tid < s) { r1[tid] += r1[tid + s]; r2[tid] += r2[tid + s]; }
        __syncthreads();
    }
    if (tid == 0) {
        const double cnt = (double)NEDGE;
        double mean = r1[0] / cnt;
        double var  = r2[0] / cnt - mean * mean;
        double a = (double)gamma[o] / sqrt(var + (double)BN_EPS);
        g_chA[o] = (float)a;
        g_chB[o] = (float)((double)beta[o] - mean * a);
    }
}

// ---------------- 9: per-point output vectors v ----------------
__global__ void v_kernel() {
    int bm = blockIdx.x;
    int od = threadIdx.x;       // 192
    int o = od / 3;
    size_t t = (size_t)bm * DTOT + od;
    size_t s = (size_t)bm * COUT + o;
    float n    = g_nrm[s];
    float scale = g_chA[o] + g_chB[o] / n;     // norm_bn / norm
    float dot  = scale * g_dfd[s];
    float pv   = scale * g_yf[t];
    float outv = pv;
    if (dot < 0.f) outv = pv - dot / (g_dsq[s] + VN_EPS) * g_yd[t];
    g_v[t] = outv;
}

// ---------------- 10: gather-mean to output ----------------
__global__ void gather_kernel(float* __restrict__ out) {
    __shared__ int sidx[16 * KNN];
    int b  = blockIdx.y;
    int n0 = blockIdx.x * 16;
    int tid = threadIdx.x;      // 192
    if (tid < 16 * KNN) sidx[tid] = g_idx[((size_t)b * NPT + n0) * KNN + tid];
    __syncthreads();

    const float* vb = g_v + (size_t)b * NPT * DTOT;
    float res[16];
    #pragma unroll
    for (int n = 0; n < 16; n++) {
        float acc = 0.f;
        #pragma unroll
        for (int k = 0; k < KNN; k++) {
            int m = sidx[n * KNN + k];
            acc += vb[(size_t)m * DTOT + tid];
        }
        res[n] = acc * (1.0f / (float)KNN);
    }
    float* ob = out + ((size_t)b * DTOT + tid) * NPT + n0;
    *(float4*)(ob)      = make_float4(res[0],  res[1],  res[2],  res[3]);
    *(float4*)(ob + 4)  = make_float4(res[4],  res[5],  res[6],  res[7]);
    *(float4*)(ob + 8)  = make_float4(res[8],  res[9],  res[10], res[11]);
    *(float4*)(ob + 12) = make_float4(res[12], res[13], res[14], res[15]);
}

// ---------------- launch ----------------
extern "C" void kernel_launch(void* const* d_in, const int* in_sizes, int n_in,
                              void* d_out, int out_size) {
    const float* x     = (const float*)d_in[0];
    const float* Wf    = (const float*)d_in[1];
    const float* Wd    = (const float*)d_in[2];
    const float* gamma = (const float*)d_in[3];
    const float* beta  = (const float*)d_in[4];
    float* out = (float*)d_out;

    xt_kernel<<<dim3(NPT / 32, DTOT / 32, BATCH), dim3(32, 32)>>>(x);
    xx64_kernel<<<NPAIR / 256, 256>>>();
    knn_wmma<<<dim3(NPT / 128, NPT / 128, BATCH), 256>>>();
    cand_kernel<<<NPAIR / 8, 256>>>();
    refine_kernel<<<NPAIR / 8, 256>>>();
    feat_kernel<<<dim3(NPT / 16, BATCH), 192>>>(x, Wf, Wd);
    pstat_kernel<<<(NPAIR * COUT) / 256, 256>>>();
    count_kernel<<<(NEDGE + 255) / 256, 256>>>();
    bnstat_kernel<<<COUT, 256>>>(gamma, beta);
    v_kernel<<<NPAIR, DTOT>>>();
    gather_kernel<<<dim3(NPT / 16, BATCH), DTOT>>>(out);
}